// round 8
// baseline (speedup 1.0000x reference)
#include <cuda_runtime.h>
#include <cuda_bf16.h>
#include <cstdint>

// Stickbreaking attention via mma.sync (HMMA) bf16-split. B=2 H=16 S=1024 D=64.
// w[i,k] = exp2( x2 + 2*lb2_ik + sum_{k<j<=i} lb2_ij ), lb2 = -log2(1+2^x2),
// x2 = logits * 0.125 * log2(e). Key blocks streamed descending, carry A (log2).
// K/V streamed via cp.async into fp32 smem staging -> 3 CTAs/SM.

#define SEQ 1024
#define DH 64
#define BQ 64
#define BK 64
#define THREADS 128
#define NQB (SEQ / BQ)
#define FULL 0xffffffffu

#define KH_OFF 0
#define KL_OFF 8192
#define VH_OFF 16384
#define VL_OFF 24576
#define ST_OFF 32768            // fp32 staging: K 16KB, then V 16KB
#define SM_TOTAL 65536

__device__ __forceinline__ uint32_t smem_u32(const void* p) {
    uint32_t a;
    asm("{ .reg .u64 t; cvta.to.shared.u64 t, %1; cvt.u32.u64 %0, t; }" : "=r"(a) : "l"(p));
    return a;
}
__device__ __forceinline__ float ex2f(float x) {
    float r; asm("ex2.approx.f32 %0, %1;" : "=f"(r) : "f"(x)); return r;
}
__device__ __forceinline__ float lg2f(float x) {
    float r; asm("lg2.approx.f32 %0, %1;" : "=f"(r) : "f"(x)); return r;
}
__device__ __forceinline__ void cp16(uint32_t dst, const void* src) {
    asm volatile("cp.async.cg.shared.global [%0], [%1], 16;" :: "r"(dst), "l"(src));
}

#define MMA(d, a, b0, b1) \
    asm volatile("mma.sync.aligned.m16n8k16.row.col.f32.bf16.bf16.f32 " \
        "{%0,%1,%2,%3}, {%4,%5,%6,%7}, {%8,%9}, {%0,%1,%2,%3};" \
        : "+f"((d)[0]), "+f"((d)[1]), "+f"((d)[2]), "+f"((d)[3]) \
        : "r"((a)[0]), "r"((a)[1]), "r"((a)[2]), "r"((a)[3]), "r"(b0), "r"(b1))

#define LDSM4(r, addr) \
    asm volatile("ldmatrix.sync.aligned.m8n8.x4.shared.b16 {%0,%1,%2,%3}, [%4];" \
        : "=r"((r)[0]), "=r"((r)[1]), "=r"((r)[2]), "=r"((r)[3]) : "r"(addr))

#define LDSM4T(r, addr) \
    asm volatile("ldmatrix.sync.aligned.m8n8.x4.trans.shared.b16 {%0,%1,%2,%3}, [%4];" \
        : "=r"((r)[0]), "=r"((r)[1]), "=r"((r)[2]), "=r"((r)[3]) : "r"(addr))

__device__ __forceinline__ uint32_t pack2(__nv_bfloat16 lo, __nv_bfloat16 hi) {
    __nv_bfloat162 t(lo, hi);
    return *reinterpret_cast<uint32_t*>(&t);
}
__device__ __forceinline__ void split2(float x, __nv_bfloat16& h, __nv_bfloat16& l) {
    h = __float2bfloat16_rn(x);
    l = __float2bfloat16_rn(x - __bfloat162float(h));
}

__global__ __launch_bounds__(THREADS, 3)
void sb_mma(const float* __restrict__ q, const float* __restrict__ k,
            const float* __restrict__ v, float* __restrict__ out) {
    extern __shared__ __align__(16) char smem[];
    const uint32_t sb = smem_u32(smem);
    const int tid = threadIdx.x;
    const int lane = tid & 31, warp = tid >> 5;
    const int q4 = lane & 3;                     // quad col idx
    const int sel = lane >> 3, rr = lane & 7;    // ldmatrix select / row

    const int idx = blockIdx.x;
    const int qb = (NQB - 1) - (idx >> 5);       // heaviest q-tiles first
    const int bh = idx & 31;
    const int qbase = qb * BQ;

    const float* qg = q + (size_t)bh * SEQ * DH;
    const float* kg = k + (size_t)bh * SEQ * DH;
    const float* vg = v + (size_t)bh * SEQ * DH;
    float* og = out + (size_t)bh * SEQ * DH;

    // ---- kick off cp.async for the first (diagonal) K/V block ----
    {
        const float4* gk = (const float4*)(kg + (size_t)(qb * BK) * DH);
        const float4* gv = (const float4*)(vg + (size_t)(qb * BK) * DH);
        #pragma unroll
        for (int i = 0; i < 8; i++) {
            int f = i * THREADS + tid;
            cp16(sb + ST_OFF + f * 16, gk + f);
            cp16(sb + ST_OFF + 16384 + f * 16, gv + f);
        }
        asm volatile("cp.async.commit_group;" ::: "memory");
    }

    // ---- stage Q tile (bf16 hi/lo) into KH/KL buffers, XOR-swizzled ----
    {
        const float4* gq = (const float4*)(qg + (size_t)qbase * DH);
        #pragma unroll
        for (int i = 0; i < 8; i++) {
            int f = i * THREADS + tid;
            int row = f >> 4, c4 = f & 15;
            float4 x = gq[f];
            __nv_bfloat16 h0, h1, h2, h3, l0, l1, l2, l3;
            split2(x.x, h0, l0); split2(x.y, h1, l1);
            split2(x.z, h2, l2); split2(x.w, h3, l3);
            uint32_t off = (uint32_t)(row * 128 + (((c4 >> 1) ^ (row & 7)) << 4) + (c4 & 1) * 8);
            *(uint2*)(smem + KH_OFF + off) = make_uint2(pack2(h0, h1), pack2(h2, h3));
            *(uint2*)(smem + KL_OFF + off) = make_uint2(pack2(l0, l1), pack2(l2, l3));
        }
    }
    __syncthreads();

    // ---- persistent Q A-fragments (hi & lo), 4 k-chunks ----
    uint32_t qh[4][4], ql[4][4];
    {
        int row = warp * 16 + (sel & 1) * 8 + rr;
        #pragma unroll
        for (int kc = 0; kc < 4; kc++) {
            int chunk = 2 * kc + (sel >> 1);
            uint32_t a = sb + (uint32_t)(row * 128 + ((chunk ^ rr) << 4));
            LDSM4(qh[kc], a + KH_OFF);
            LDSM4(ql[kc], a + KL_OFF);
        }
    }

    float o[8][4];
    #pragma unroll
    for (int nt = 0; nt < 8; nt++) { o[nt][0] = o[nt][1] = o[nt][2] = o[nt][3] = 0.f; }
    float A0 = 0.f, A1 = 0.f;                    // log2-domain carries
    const int wr0 = qbase + warp * 16 + (lane >> 2);

    #pragma unroll 1
    for (int kb = qb; kb >= 0; --kb) {
        const int kbase = kb * BK;

        asm volatile("cp.async.wait_group 0;" ::: "memory");
        __syncthreads();   // staging visible to all; prev iter smem reads done

        // -- convert staging fp32 -> bf16 hi/lo buffers (LDS + STS) --
        {
            const float4* stK = (const float4*)(smem + ST_OFF);
            const float4* stV = (const float4*)(smem + ST_OFF + 16384);
            #pragma unroll
            for (int i = 0; i < 8; i++) {
                int f = i * THREADS + tid;
                int row = f >> 4, c4 = f & 15;
                uint32_t off = (uint32_t)(row * 128 + (((c4 >> 1) ^ (row & 7)) << 4) + (c4 & 1) * 8);
                float4 kx = stK[f], vx = stV[f];
                __nv_bfloat16 h0, h1, h2, h3, l0, l1, l2, l3;
                split2(kx.x, h0, l0); split2(kx.y, h1, l1);
                split2(kx.z, h2, l2); split2(kx.w, h3, l3);
                *(uint2*)(smem + KH_OFF + off) = make_uint2(pack2(h0, h1), pack2(h2, h3));
                *(uint2*)(smem + KL_OFF + off) = make_uint2(pack2(l0, l1), pack2(l2, l3));
                split2(vx.x, h0, l0); split2(vx.y, h1, l1);
                split2(vx.z, h2, l2); split2(vx.w, h3, l3);
                *(uint2*)(smem + VH_OFF + off) = make_uint2(pack2(h0, h1), pack2(h2, h3));
                *(uint2*)(smem + VL_OFF + off) = make_uint2(pack2(l0, l1), pack2(l2, l3));
            }
        }
        __syncthreads();   // bf16 tiles visible; staging fully consumed

        // -- issue next block's cp.async (covered by QK + scan + PV) --
        if (kb > 0) {
            const float4* gk = (const float4*)(kg + (size_t)(kbase - BK) * DH);
            const float4* gv = (const float4*)(vg + (size_t)(kbase - BK) * DH);
            #pragma unroll
            for (int i = 0; i < 8; i++) {
                int f = i * THREADS + tid;
                cp16(sb + ST_OFF + f * 16, gk + f);
                cp16(sb + ST_OFF + 16384 + f * 16, gv + f);
            }
            asm volatile("cp.async.commit_group;" ::: "memory");
        }

        // ---- QK^T: D[16 rows x 64 keys], 3 split passes ----
        float d[8][4];
        #pragma unroll
        for (int nt = 0; nt < 8; nt++) { d[nt][0] = d[nt][1] = d[nt][2] = d[nt][3] = 0.f; }

        #pragma unroll
        for (int kc = 0; kc < 4; kc++) {
            uint32_t kf[16];
            const int keyl = (sel >> 1) * 8 + rr;
            const int chunk = 2 * kc + (sel & 1);
            #pragma unroll
            for (int p = 0; p < 4; p++) {
                uint32_t a = sb + KH_OFF + (uint32_t)((p * 16 + keyl) * 128 + ((chunk ^ rr) << 4));
                LDSM4(&kf[p * 4], a);
            }
            #pragma unroll
            for (int nt = 0; nt < 8; nt++) MMA(d[nt], qh[kc], kf[nt * 2], kf[nt * 2 + 1]);
            #pragma unroll
            for (int nt = 0; nt < 8; nt++) MMA(d[nt], ql[kc], kf[nt * 2], kf[nt * 2 + 1]);
            #pragma unroll
            for (int p = 0; p < 4; p++) {
                uint32_t a = sb + KL_OFF + (uint32_t)((p * 16 + keyl) * 128 + ((chunk ^ rr) << 4));
                LDSM4(&kf[p * 4], a);
            }
            #pragma unroll
            for (int nt = 0; nt < 8; nt++) MMA(d[nt], qh[kc], kf[nt * 2], kf[nt * 2 + 1]);
        }

        // ---- stickbreaking scan (log2 domain, quad shuffles) ----
        uint32_t wha[4][4], wla[4][4];
        const bool diag = (kb == qb);
        const float SC = 0.18033688f;   // 0.125 * log2(e)
        #pragma unroll
        for (int nt = 7; nt >= 0; --nt) {
            const int keyA = kbase + nt * 8 + 2 * q4;
            #pragma unroll
            for (int rs = 0; rs < 2; rs++) {
                float xa = d[nt][rs * 2 + 0] * SC;
                float xb = d[nt][rs * 2 + 1] * SC;
                float la = -lg2f(1.f + ex2f(xa));
                float lb = -lg2f(1.f + ex2f(xb));
                float ca = xa + la, cb = xb + lb;
                if (diag) {
                    const int rowg = wr0 + rs * 8;
                    if (keyA > rowg)     { la = 0.f; ca = -1e30f; }
                    if (keyA + 1 > rowg) { lb = 0.f; cb = -1e30f; }
                }
                float s2 = la + lb;
                float u = s2;                                  // quad suffix scan
                float t1 = __shfl_down_sync(FULL, u, 1, 4);
                u = (q4 < 3) ? u + t1 : u;
                float t2 = __shfl_down_sync(FULL, u, 2, 4);
                u = (q4 < 2) ? u + t2 : u;
                float tot = __shfl_sync(FULL, u, 0, 4);
                float& A = rs ? A1 : A0;
                float hi = A + (u - s2);                       // lb2 of higher lanes
                float wb = ex2f(cb + lb + hi);
                float wa = ex2f(ca + la + lb + hi);
                A += tot;
                __nv_bfloat16 ah, al, bh2, bl2;
                split2(wa, ah, al); split2(wb, bh2, bl2);
                wha[nt >> 1][(nt & 1) * 2 + rs] = pack2(ah, bh2);
                wla[nt >> 1][(nt & 1) * 2 + rs] = pack2(al, bl2);
            }
        }

        // ---- PV: O += W * V (V via ldmatrix.trans), 3 split passes ----
        #pragma unroll
        for (int kc = 0; kc < 4; kc++) {
            uint32_t vf[16];
            const int keyv = kc * 16 + (sel & 1) * 8 + rr;
            #pragma unroll
            for (int p = 0; p < 4; p++) {
                int chunk = 2 * p + (sel >> 1);
                uint32_t a = sb + VH_OFF + (uint32_t)(keyv * 128 + ((chunk ^ rr) << 4));
                LDSM4T(&vf[p * 4], a);
            }
            #pragma unroll
            for (int nt = 0; nt < 8; nt++) MMA(o[nt], wha[kc], vf[nt * 2], vf[nt * 2 + 1]);
            #pragma unroll
            for (int nt = 0; nt < 8; nt++) MMA(o[nt], wla[kc], vf[nt * 2], vf[nt * 2 + 1]);
            #pragma unroll
            for (int p = 0; p < 4; p++) {
                int chunk = 2 * p + (sel >> 1);
                uint32_t a = sb + VL_OFF + (uint32_t)(keyv * 128 + ((chunk ^ rr) << 4));
                LDSM4T(&vf[p * 4], a);
            }
            #pragma unroll
            for (int nt = 0; nt < 8; nt++) MMA(o[nt], wha[kc], vf[nt * 2], vf[nt * 2 + 1]);
        }
    }

    // ---- write output: per-thread 2 rows x 16 cols as float2 ----
    {
        float* r0p = og + (size_t)wr0 * DH;
        float* r1p = og + (size_t)(wr0 + 8) * DH;
        #pragma unroll
        for (int nt = 0; nt < 8; nt++) {
            *(float2*)(r0p + nt * 8 + 2 * q4) = make_float2(o[nt][0], o[nt][1]);
            *(float2*)(r1p + nt * 8 + 2 * q4) = make_float2(o[nt][2], o[nt][3]);
        }
    }
}

extern "C" void kernel_launch(void* const* d_in, const int* in_sizes, int n_in,
                              void* d_out, int out_size) {
    const float* q = (const float*)d_in[0];
    const float* k = (const float*)d_in[1];
    const float* v = (const float*)d_in[2];
    float* out = (float*)d_out;
    (void)in_sizes; (void)n_in; (void)out_size;

    cudaFuncSetAttribute(sb_mma, cudaFuncAttributeMaxDynamicSharedMemorySize, SM_TOTAL);
    sb_mma<<<NQB * 32, THREADS, SM_TOTAL>>>(q, k, v, out);  // 512 CTAs, heaviest first
}

// round 9
// speedup vs baseline: 1.0897x; 1.0897x over previous
#include <cuda_runtime.h>
#include <cuda_bf16.h>
#include <cstdint>

// Stickbreaking attention via mma.sync (HMMA) bf16-split. B=2 H=16 S=1024 D=64.
// Linear-domain: z = sigmoid(x), beta = 1-z; w[i,k] = z_ik*beta_ik*prod_{k<j<=i} beta_ij.
// Key blocks streamed descending with multiplicative carry P per row.
// Double-buffered bf16 K/V tiles: one __syncthreads per iteration.

#define SEQ 1024
#define DH 64
#define BQ 64
#define BK 64
#define THREADS 128
#define NQB (SEQ / BQ)
#define FULL 0xffffffffu

#define BUFSZ 32768       // per buffer: KH 8K, KL 8K, VH 8K, VL 8K
#define KH_O 0
#define KL_O 8192
#define VH_O 16384
#define VL_O 24576
#define SM_TOTAL 65536

__device__ __forceinline__ uint32_t smem_u32(const void* p) {
    uint32_t a;
    asm("{ .reg .u64 t; cvta.to.shared.u64 t, %1; cvt.u32.u64 %0, t; }" : "=r"(a) : "l"(p));
    return a;
}
__device__ __forceinline__ float ex2f(float x) {
    float r; asm("ex2.approx.f32 %0, %1;" : "=f"(r) : "f"(x)); return r;
}
__device__ __forceinline__ float rcpf(float x) {
    float r; asm("rcp.approx.f32 %0, %1;" : "=f"(r) : "f"(x)); return r;
}

#define MMA(d, a, b0, b1) \
    asm volatile("mma.sync.aligned.m16n8k16.row.col.f32.bf16.bf16.f32 " \
        "{%0,%1,%2,%3}, {%4,%5,%6,%7}, {%8,%9}, {%0,%1,%2,%3};" \
        : "+f"((d)[0]), "+f"((d)[1]), "+f"((d)[2]), "+f"((d)[3]) \
        : "r"((a)[0]), "r"((a)[1]), "r"((a)[2]), "r"((a)[3]), "r"(b0), "r"(b1))

#define LDSM4(r, addr) \
    asm volatile("ldmatrix.sync.aligned.m8n8.x4.shared.b16 {%0,%1,%2,%3}, [%4];" \
        : "=r"((r)[0]), "=r"((r)[1]), "=r"((r)[2]), "=r"((r)[3]) : "r"(addr))

#define LDSM4T(r, addr) \
    asm volatile("ldmatrix.sync.aligned.m8n8.x4.trans.shared.b16 {%0,%1,%2,%3}, [%4];" \
        : "=r"((r)[0]), "=r"((r)[1]), "=r"((r)[2]), "=r"((r)[3]) : "r"(addr))

__device__ __forceinline__ uint32_t pack2(__nv_bfloat16 lo, __nv_bfloat16 hi) {
    __nv_bfloat162 t(lo, hi);
    return *reinterpret_cast<uint32_t*>(&t);
}
__device__ __forceinline__ void split2(float x, __nv_bfloat16& h, __nv_bfloat16& l) {
    h = __float2bfloat16_rn(x);
    l = __float2bfloat16_rn(x - __bfloat162float(h));
}

// convert one K/V block (fp32 regs) -> bf16 hi/lo tiles at smem buffer base
__device__ __forceinline__ void conv_kv(char* smem, uint32_t base,
                                        const float4* kr, const float4* vr, int tid) {
    #pragma unroll
    for (int i = 0; i < 8; i++) {
        int f = i * THREADS + tid;
        int row = f >> 4, c4 = f & 15;
        uint32_t off = base + (uint32_t)(row * 128 + (((c4 >> 1) ^ (row & 7)) << 4) + (c4 & 1) * 8);
        __nv_bfloat16 h0, h1, h2, h3, l0, l1, l2, l3;
        split2(kr[i].x, h0, l0); split2(kr[i].y, h1, l1);
        split2(kr[i].z, h2, l2); split2(kr[i].w, h3, l3);
        *(uint2*)(smem + KH_O + off) = make_uint2(pack2(h0, h1), pack2(h2, h3));
        *(uint2*)(smem + KL_O + off) = make_uint2(pack2(l0, l1), pack2(l2, l3));
        split2(vr[i].x, h0, l0); split2(vr[i].y, h1, l1);
        split2(vr[i].z, h2, l2); split2(vr[i].w, h3, l3);
        *(uint2*)(smem + VH_O + off) = make_uint2(pack2(h0, h1), pack2(h2, h3));
        *(uint2*)(smem + VL_O + off) = make_uint2(pack2(l0, l1), pack2(l2, l3));
    }
}

__global__ __launch_bounds__(THREADS)
void sb_mma(const float* __restrict__ q, const float* __restrict__ k,
            const float* __restrict__ v, float* __restrict__ out) {
    extern __shared__ __align__(16) char smem[];
    const uint32_t sb = smem_u32(smem);
    const int tid = threadIdx.x;
    const int lane = tid & 31, warp = tid >> 5;
    const int q4 = lane & 3;                     // quad col idx
    const int sel = lane >> 3, rr = lane & 7;    // ldmatrix select / row

    const int idx = blockIdx.x;
    const int qb = (NQB - 1) - (idx >> 5);       // heaviest q-tiles first
    const int bh = idx & 31;
    const int qbase = qb * BQ;

    const float* qg = q + (size_t)bh * SEQ * DH;
    const float* kg = k + (size_t)bh * SEQ * DH;
    const float* vg = v + (size_t)bh * SEQ * DH;
    float* og = out + (size_t)bh * SEQ * DH;

    // ---- load first K/V block (qb) into registers ----
    float4 kr[8], vr[8];
    {
        const float4* gk = (const float4*)(kg + (size_t)(qb * BK) * DH);
        const float4* gv = (const float4*)(vg + (size_t)(qb * BK) * DH);
        #pragma unroll
        for (int i = 0; i < 8; i++) {
            int f = i * THREADS + tid;
            kr[i] = gk[f]; vr[i] = gv[f];
        }
    }

    // ---- stage Q tile (bf16 hi/lo) into buf0 KH/KL, XOR-swizzled ----
    {
        const float4* gq = (const float4*)(qg + (size_t)qbase * DH);
        #pragma unroll
        for (int i = 0; i < 8; i++) {
            int f = i * THREADS + tid;
            int row = f >> 4, c4 = f & 15;
            float4 x = gq[f];
            __nv_bfloat16 h0, h1, h2, h3, l0, l1, l2, l3;
            split2(x.x, h0, l0); split2(x.y, h1, l1);
            split2(x.z, h2, l2); split2(x.w, h3, l3);
            uint32_t off = (uint32_t)(row * 128 + (((c4 >> 1) ^ (row & 7)) << 4) + (c4 & 1) * 8);
            *(uint2*)(smem + KH_O + off) = make_uint2(pack2(h0, h1), pack2(h2, h3));
            *(uint2*)(smem + KL_O + off) = make_uint2(pack2(l0, l1), pack2(l2, l3));
        }
    }
    __syncthreads();

    // ---- persistent Q A-fragments (hi & lo), 4 k-chunks ----
    uint32_t qh[4][4], ql[4][4];
    {
        int row = warp * 16 + (sel & 1) * 8 + rr;
        #pragma unroll
        for (int kc = 0; kc < 4; kc++) {
            int chunk = 2 * kc + (sel >> 1);
            uint32_t a = sb + (uint32_t)(row * 128 + ((chunk ^ rr) << 4));
            LDSM4(qh[kc], a + KH_O);
            LDSM4(ql[kc], a + KL_O);
        }
    }
    __syncthreads();   // Q fragments extracted before buf0 is overwritten

    // ---- convert block qb into buf0; start LDG for qb-1 ----
    conv_kv(smem, 0, kr, vr, tid);
    if (qb > 0) {
        const float4* gk = (const float4*)(kg + (size_t)((qb - 1) * BK) * DH);
        const float4* gv = (const float4*)(vg + (size_t)((qb - 1) * BK) * DH);
        #pragma unroll
        for (int i = 0; i < 8; i++) {
            int f = i * THREADS + tid;
            kr[i] = gk[f]; vr[i] = gv[f];
        }
    }
    __syncthreads();   // buf0 visible

    float o[8][4];
    #pragma unroll
    for (int nt = 0; nt < 8; nt++) { o[nt][0] = o[nt][1] = o[nt][2] = o[nt][3] = 0.f; }
    float P0 = 1.f, P1 = 1.f;                    // multiplicative carries
    const int wr0 = qbase + warp * 16 + (lane >> 2);
    const float SC = 0.18033688f;                // 0.125 * log2(e)

    #pragma unroll 1
    for (int kb = qb; kb >= 0; --kb) {
        const int kbase = kb * BK;
        const uint32_t bufo = (uint32_t)(((qb - kb) & 1) ? BUFSZ : 0);
        const uint32_t bsb = sb + bufo;

        // ---- QK^T: D[16 rows x 64 keys], 3 split passes ----
        float d[8][4];
        #pragma unroll
        for (int nt = 0; nt < 8; nt++) { d[nt][0] = d[nt][1] = d[nt][2] = d[nt][3] = 0.f; }

        #pragma unroll
        for (int kc = 0; kc < 4; kc++) {
            uint32_t kf[16];
            const int keyl = (sel >> 1) * 8 + rr;
            const int chunk = 2 * kc + (sel & 1);
            #pragma unroll
            for (int p = 0; p < 4; p++) {
                uint32_t a = bsb + KH_O + (uint32_t)((p * 16 + keyl) * 128 + ((chunk ^ rr) << 4));
                LDSM4(&kf[p * 4], a);
            }
            #pragma unroll
            for (int nt = 0; nt < 8; nt++) MMA(d[nt], qh[kc], kf[nt * 2], kf[nt * 2 + 1]);
            #pragma unroll
            for (int nt = 0; nt < 8; nt++) MMA(d[nt], ql[kc], kf[nt * 2], kf[nt * 2 + 1]);
            #pragma unroll
            for (int p = 0; p < 4; p++) {
                uint32_t a = bsb + KL_O + (uint32_t)((p * 16 + keyl) * 128 + ((chunk ^ rr) << 4));
                LDSM4(&kf[p * 4], a);
            }
            #pragma unroll
            for (int nt = 0; nt < 8; nt++) MMA(d[nt], qh[kc], kf[nt * 2], kf[nt * 2 + 1]);
        }

        // ---- stickbreaking scan: linear domain, suffix product over quad ----
        uint32_t wha[4][4], wla[4][4];
        const bool diag = (kb == qb);
        #pragma unroll
        for (int nt = 7; nt >= 0; --nt) {
            const int keyA = kbase + nt * 8 + 2 * q4;
            #pragma unroll
            for (int rs = 0; rs < 2; rs++) {
                float x2a = d[nt][rs * 2 + 0] * SC;
                float x2b = d[nt][rs * 2 + 1] * SC;
                float ta = ex2f(-x2a), tb = ex2f(-x2b);
                float za = rcpf(1.f + ta), zb = rcpf(1.f + tb);
                float ba = 1.f - za, bb = 1.f - zb;
                if (diag) {
                    const int rowg = wr0 + rs * 8;
                    if (keyA > rowg)     { za = 0.f; ba = 1.f; }
                    if (keyA + 1 > rowg) { zb = 0.f; bb = 1.f; }
                }
                float pp = ba * bb;
                float u = pp;                               // inclusive suffix product
                float t1 = __shfl_down_sync(FULL, u, 1, 4);
                u = (q4 < 3) ? u * t1 : u;
                float t2 = __shfl_down_sync(FULL, u, 2, 4);
                u = (q4 < 2) ? u * t2 : u;
                float ue = __shfl_down_sync(FULL, u, 1, 4); // exclusive (lanes above)
                ue = (q4 < 3) ? ue : 1.f;
                float tot = __shfl_sync(FULL, u, 0, 4);
                float& P = rs ? P1 : P0;
                float R  = P * ue;                          // betas of all higher keys
                float Rb = bb * R;
                float wb = zb * Rb;
                float Ra = ba * Rb;
                float wa = za * Ra;
                P *= tot;
                __nv_bfloat16 ah, al, bh2, bl2;
                split2(wa, ah, al); split2(wb, bh2, bl2);
                wha[nt >> 1][(nt & 1) * 2 + rs] = pack2(ah, bh2);
                wla[nt >> 1][(nt & 1) * 2 + rs] = pack2(al, bl2);
            }
        }

        // ---- convert next block into the other buffer; issue following LDGs ----
        if (kb > 0) {
            conv_kv(smem + (bufo ^ BUFSZ), 0, kr, vr, tid);
            if (kb > 1) {
                const float4* gk = (const float4*)(kg + (size_t)((kb - 2) * BK) * DH);
                const float4* gv = (const float4*)(vg + (size_t)((kb - 2) * BK) * DH);
                #pragma unroll
                for (int i = 0; i < 8; i++) {
                    int f = i * THREADS + tid;
                    kr[i] = gk[f]; vr[i] = gv[f];
                }
            }
        }

        // ---- PV: O += W * V (V via ldmatrix.trans), 3 split passes ----
        #pragma unroll
        for (int kc = 0; kc < 4; kc++) {
            uint32_t vf[16];
            const int keyv = kc * 16 + (sel & 1) * 8 + rr;
            #pragma unroll
            for (int p = 0; p < 4; p++) {
                int chunk = 2 * p + (sel >> 1);
                uint32_t a = bsb + VH_O + (uint32_t)(keyv * 128 + ((chunk ^ rr) << 4));
                LDSM4T(&vf[p * 4], a);
            }
            #pragma unroll
            for (int nt = 0; nt < 8; nt++) MMA(o[nt], wha[kc], vf[nt * 2], vf[nt * 2 + 1]);
            #pragma unroll
            for (int nt = 0; nt < 8; nt++) MMA(o[nt], wla[kc], vf[nt * 2], vf[nt * 2 + 1]);
            #pragma unroll
            for (int p = 0; p < 4; p++) {
                int chunk = 2 * p + (sel >> 1);
                uint32_t a = bsb + VL_O + (uint32_t)(keyv * 128 + ((chunk ^ rr) << 4));
                LDSM4T(&vf[p * 4], a);
            }
            #pragma unroll
            for (int nt = 0; nt < 8; nt++) MMA(o[nt], wha[kc], vf[nt * 2], vf[nt * 2 + 1]);
        }

        __syncthreads();   // single barrier: buf[p] reads done, buf[p^1] writes visible
    }

    // ---- write output: per-thread 2 rows x 16 cols as float2 ----
    {
        float* r0p = og + (size_t)wr0 * DH;
        float* r1p = og + (size_t)(wr0 + 8) * DH;
        #pragma unroll
        for (int nt = 0; nt < 8; nt++) {
            *(float2*)(r0p + nt * 8 + 2 * q4) = make_float2(o[nt][0], o[nt][1]);
            *(float2*)(r1p + nt * 8 + 2 * q4) = make_float2(o[nt][2], o[nt][3]);
        }
    }
}

extern "C" void kernel_launch(void* const* d_in, const int* in_sizes, int n_in,
                              void* d_out, int out_size) {
    const float* q = (const float*)d_in[0];
    const float* k = (const float*)d_in[1];
    const float* v = (const float*)d_in[2];
    float* out = (float*)d_out;
    (void)in_sizes; (void)n_in; (void)out_size;

    cudaFuncSetAttribute(sb_mma, cudaFuncAttributeMaxDynamicSharedMemorySize, SM_TOTAL);
    sb_mma<<<NQB * 32, THREADS, SM_TOTAL>>>(q, k, v, out);  // 512 CTAs, heaviest first
}